// round 9
// baseline (speedup 1.0000x reference)
#include <cuda_runtime.h>
#include <math.h>

#define DINL __device__ __forceinline__

constexpr int NN  = 100000;
constexpr int EE  = 1600000;
constexpr int EP  = EE + NN;
constexpr int HH  = 4;
constexpr int CC  = 32;
constexpr int HC  = 128;
constexpr int EDD = 16;
constexpr float SLOPE = 0.2f;

// ---------------- scratch ----------------
__device__ float g_h1[NN * HC];
__device__ float g_x1[NN * HC];
__device__ float g_g2[NN * CC];
__device__ float g_alS1[NN * HH], g_alD1[NN * HH];
__device__ float g_alS2[NN],      g_alD2[NN];
__device__ float g_alE1[EE * HH];
__device__ float g_alE2[EE];
__device__ float g_v1e[EDD * HH];
__device__ float g_v2e[EDD];
__device__ int   g_deg[NN];
__device__ float g_aes1[NN * HH];
__device__ float g_aes2[NN];
__device__ float g_es1[NN * HH];
__device__ float g_z1[NN * HH];
__device__ float g_es2[NN];
__device__ float g_z2[NN];
__device__ float g_agg1[NN * HC];
__device__ float g_agg2[NN * CC];

DINL float lrelu1(float x) { return x >= 0.f ? x : SLOPE * x; }
DINL float elu1(float x)   { return x > 0.f ? x : expm1f(x); }

// ---------------- zero scratch ----------------
__global__ void k_zero() {
    int t = blockIdx.x * blockDim.x + threadIdx.x;
    int stride = gridDim.x * blockDim.x;
    for (int i = t; i < NN * HC; i += stride) g_agg1[i] = 0.f;
    for (int i = t; i < NN * CC; i += stride) g_agg2[i] = 0.f;
    for (int i = t; i < NN * HH; i += stride) g_aes1[i] = 0.f;
    for (int i = t; i < NN;      i += stride) { g_aes2[i] = 0.f; g_deg[i] = 0; }
}

// ---------------- fold: v = We . a_e ----------------
__global__ void k_prep(const float* __restrict__ W1e, const float* __restrict__ a1e,
                       const float* __restrict__ W2e, const float* __restrict__ a2e) {
    int t = threadIdx.x;
    if (t < EDD * HH) {
        int d = t >> 2, h = t & 3;
        float s = 0.f;
        for (int c = 0; c < CC; c++) s += W1e[d * HC + h * CC + c] * a1e[h * CC + c];
        g_v1e[d * HH + h] = s;
    }
    if (t < EDD) {
        float s = 0.f;
        for (int c = 0; c < CC; c++) s += W2e[t * CC + c] * a2e[c];
        g_v2e[t] = s;
    }
}

// ---------------- per-edge logit contributions from edge_attr ----------------
__global__ void k_edge_al(const float* __restrict__ eattr) {
    int e = blockIdx.x * blockDim.x + threadIdx.x;
    if (e >= EE) return;
    const float* ea = eattr + e * EDD;
    float a0 = 0.f, a1 = 0.f, a2 = 0.f, a3 = 0.f, s2 = 0.f;
    #pragma unroll
    for (int d = 0; d < EDD; d++) {
        float ev = ea[d];
        a0 += ev * g_v1e[d * 4 + 0];
        a1 += ev * g_v1e[d * 4 + 1];
        a2 += ev * g_v1e[d * 4 + 2];
        a3 += ev * g_v1e[d * 4 + 3];
        s2 += ev * g_v2e[d];
    }
    g_alE1[e * 4 + 0] = a0;
    g_alE1[e * 4 + 1] = a1;
    g_alE1[e * 4 + 2] = a2;
    g_alE1[e * 4 + 3] = a3;
    g_alE2[e] = s2;
}

// ---------------- naive matmuls ----------------
__global__ void k_mm1(const float* __restrict__ x, const float* __restrict__ W1) {
    int t = blockIdx.x * blockDim.x + threadIdx.x;
    if (t >= NN * HC) return;
    int n = t >> 7, j = t & 127;
    const float* xr = x + n * HC;
    float s = 0.f;
    #pragma unroll 8
    for (int k = 0; k < 128; k++) s += xr[k] * W1[k * HC + j];
    g_h1[t] = s;
}
__global__ void k_mm2(const float* __restrict__ W2) {
    int t = blockIdx.x * blockDim.x + threadIdx.x;
    if (t >= NN * CC) return;
    int n = t >> 5, j = t & 31;
    const float* xr = g_x1 + n * HC;
    float s = 0.f;
    #pragma unroll 8
    for (int k = 0; k < 128; k++) s += xr[k] * W2[k * CC + j];
    g_g2[t] = s;
}

// ---------------- per-node src/dst attention scalars ----------------
__global__ void k_nodal1(const float* __restrict__ a1s, const float* __restrict__ a1d) {
    int t = blockIdx.x * blockDim.x + threadIdx.x;
    if (t >= NN * HH) return;
    int n = t >> 2, h = t & 3;
    float s = 0.f, d = 0.f;
    for (int c = 0; c < CC; c++) {
        float hv = g_h1[n * HC + h * CC + c];
        s += hv * a1s[h * CC + c];
        d += hv * a1d[h * CC + c];
    }
    g_alS1[t] = s;
    g_alD1[t] = d;
}
__global__ void k_nodal2(const float* __restrict__ a2s, const float* __restrict__ a2d) {
    int n = blockIdx.x * blockDim.x + threadIdx.x;
    if (n >= NN) return;
    float s = 0.f, d = 0.f;
    for (int c = 0; c < CC; c++) {
        float gv = g_g2[n * CC + c];
        s += gv * a2s[c];
        d += gv * a2d[c];
    }
    g_alS2[n] = s;
    g_alD2[n] = d;
}

// ---------------- degree + sum of edge logit contributions per dst ----------------
__global__ void k_degsum(const int* __restrict__ ei) {
    int e = blockIdx.x * blockDim.x + threadIdx.x;
    if (e >= EE) return;
    int d = ei[EE + e];
    atomicAdd(&g_deg[d], 1);
    atomicAdd(&g_aes1[d * 4 + 0], g_alE1[e * 4 + 0]);
    atomicAdd(&g_aes1[d * 4 + 1], g_alE1[e * 4 + 1]);
    atomicAdd(&g_aes1[d * 4 + 2], g_alE1[e * 4 + 2]);
    atomicAdd(&g_aes1[d * 4 + 3], g_alE1[e * 4 + 3]);
    atomicAdd(&g_aes2[d], g_alE2[e]);
}

// ---------------- self-loop logits, init z with self term ----------------
__global__ void k_self1() {
    int t = blockIdx.x * blockDim.x + threadIdx.x;
    if (t >= NN * HH) return;
    int n = t >> 2;
    int dg = g_deg[n];
    float inv = 1.f / (float)(dg > 0 ? dg : 1);
    float es = lrelu1(g_alS1[t] + g_alD1[t] + g_aes1[t] * inv);
    g_es1[t] = es;
    g_z1[t]  = __expf(es);
}
__global__ void k_self2() {
    int n = blockIdx.x * blockDim.x + threadIdx.x;
    if (n >= NN) return;
    int dg = g_deg[n];
    float inv = 1.f / (float)(dg > 0 ? dg : 1);
    float es = lrelu1(g_alS2[n] + g_alD2[n] + g_aes2[n] * inv);
    g_es2[n] = es;
    g_z2[n]  = __expf(es);
}

// ---------------- softmax denominators (edge terms) ----------------
__global__ void k_z1(const int* __restrict__ ei) {
    int e = blockIdx.x * blockDim.x + threadIdx.x;
    if (e >= EE) return;
    int s = ei[e], d = ei[EE + e];
    #pragma unroll
    for (int h = 0; h < HH; h++) {
        float el = lrelu1(g_alS1[s * 4 + h] + g_alD1[d * 4 + h] + g_alE1[e * 4 + h]);
        atomicAdd(&g_z1[d * 4 + h], __expf(el));
    }
}
__global__ void k_z2(const int* __restrict__ ei) {
    int e = blockIdx.x * blockDim.x + threadIdx.x;
    if (e >= EE) return;
    int s = ei[e], d = ei[EE + e];
    float el = lrelu1(g_alS2[s] + g_alD2[d] + g_alE2[e]);
    atomicAdd(&g_z2[d], __expf(el));
}

// ---------------- aggregation (warp per edge) ----------------
__global__ void k_agg1(const int* __restrict__ ei) {
    int g = (blockIdx.x * blockDim.x + threadIdx.x) >> 5;
    int lane = threadIdx.x & 31;
    if (g >= EE) return;
    int s = ei[g], d = ei[EE + g];
    int h = lane >> 3;
    float el = lrelu1(g_alS1[s * 4 + h] + g_alD1[d * 4 + h] + g_alE1[g * 4 + h]);
    float alpha = __expf(el) / g_z1[d * 4 + h];
    float4 hv = *(const float4*)&g_h1[s * HC + lane * 4];
    atomicAdd(&g_agg1[d * HC + lane * 4 + 0], alpha * hv.x);
    atomicAdd(&g_agg1[d * HC + lane * 4 + 1], alpha * hv.y);
    atomicAdd(&g_agg1[d * HC + lane * 4 + 2], alpha * hv.z);
    atomicAdd(&g_agg1[d * HC + lane * 4 + 3], alpha * hv.w);
}
__global__ void k_agg2(const int* __restrict__ ei, float* __restrict__ alphaOut) {
    int g = (blockIdx.x * blockDim.x + threadIdx.x) >> 5;
    int lane = threadIdx.x & 31;
    if (g >= EE) return;
    int s = ei[g], d = ei[EE + g];
    float el = lrelu1(g_alS2[s] + g_alD2[d] + g_alE2[g]);
    float alpha = __expf(el) / g_z2[d];
    atomicAdd(&g_agg2[d * CC + lane], alpha * g_g2[s * CC + lane]);
    if (alphaOut != nullptr && lane == 0) alphaOut[g] = alpha;
}

// ---------------- finish layers (add self-loop term + bias + elu) ----------------
__global__ void k_fin1(const float* __restrict__ b1) {
    int t = blockIdx.x * blockDim.x + threadIdx.x;
    if (t >= NN * HC) return;
    int n = t >> 7, j = t & 127, h = j >> 5;
    float aSelf = __expf(g_es1[n * 4 + h]) / g_z1[n * 4 + h];
    g_x1[t] = elu1(g_agg1[t] + aSelf * g_h1[t] + b1[j]);
}
__global__ void k_fin2(const float* __restrict__ b2, float* __restrict__ h2out,
                       float* __restrict__ alphaOut) {
    int t = blockIdx.x * blockDim.x + threadIdx.x;
    if (t >= NN * CC) return;
    int n = t >> 5, j = t & 31;
    float aSelf = __expf(g_es2[n]) / g_z2[n];
    h2out[t] = elu1(g_agg2[t] + aSelf * g_g2[t] + b2[j]);
    if (alphaOut != nullptr && j == 0) alphaOut[EE + n] = aSelf;
}

// ---------------- edge_index output (as float) ----------------
__global__ void k_write_ei(const int* __restrict__ ei, float* __restrict__ out) {
    int t = blockIdx.x * blockDim.x + threadIdx.x;
    if (t >= EP) return;
    float sv = (t < EE) ? (float)ei[t]      : (float)(t - EE);
    float dv = (t < EE) ? (float)ei[EE + t] : (float)(t - EE);
    out[t] = sv;
    out[EP + t] = dv;
}

// ---------------- launch ----------------
extern "C" void kernel_launch(void* const* d_in, const int* in_sizes, int n_in,
                              void* d_out, int out_size) {
    const float* x    = (const float*)d_in[0];
    const int*   ei   = (const int*)d_in[1];
    const float* eattr= (const float*)d_in[2];
    const float* W1   = (const float*)d_in[3];
    const float* W1e  = (const float*)d_in[4];
    const float* a1s  = (const float*)d_in[5];
    const float* a1d  = (const float*)d_in[6];
    const float* a1e  = (const float*)d_in[7];
    const float* b1   = (const float*)d_in[8];
    const float* W2   = (const float*)d_in[9];
    const float* W2e  = (const float*)d_in[10];
    const float* a2s  = (const float*)d_in[11];
    const float* a2d  = (const float*)d_in[12];
    const float* a2e  = (const float*)d_in[13];
    const float* b2   = (const float*)d_in[14];
    float* out = (float*)d_out;

    bool hasEI = out_size >= NN * CC + 2 * EP;
    bool hasAl = out_size >= NN * CC + 2 * EP + EP;
    float* h2out  = out;
    float* eiout  = hasEI ? out + NN * CC : nullptr;
    float* alphaO = hasAl ? out + NN * CC + 2 * EP : nullptr;

    k_zero   <<<2048, 256>>>();
    k_prep   <<<1, 64>>>(W1e, a1e, W2e, a2e);
    k_edge_al<<<(EE + 255) / 256, 256>>>(eattr);

    // layer 1
    k_mm1    <<<(NN * HC + 255) / 256, 256>>>(x, W1);
    k_nodal1 <<<(NN * HH + 255) / 256, 256>>>(a1s, a1d);
    k_degsum <<<(EE + 255) / 256, 256>>>(ei);
    k_self1  <<<(NN * HH + 255) / 256, 256>>>();
    k_z1     <<<(EE + 255) / 256, 256>>>(ei);
    k_agg1   <<<(EE * 32 + 255) / 256, 256>>>(ei);
    k_fin1   <<<(NN * HC + 255) / 256, 256>>>(b1);

    // layer 2
    k_mm2    <<<(NN * CC + 255) / 256, 256>>>(W2);
    k_nodal2 <<<(NN + 255) / 256, 256>>>(a2s, a2d);
    k_self2  <<<(NN + 255) / 256, 256>>>();
    k_z2     <<<(EE + 255) / 256, 256>>>(ei);
    k_agg2   <<<(EE * 32 + 255) / 256, 256>>>(ei, alphaO);
    k_fin2   <<<(NN * CC + 255) / 256, 256>>>(b2, h2out, alphaO);

    if (eiout) k_write_ei<<<(EP + 255) / 256, 256>>>(ei, eiout);
}

// round 12
// speedup vs baseline: 1.5055x; 1.5055x over previous
#include <cuda_runtime.h>
#include <math.h>

#define DINL __device__ __forceinline__

constexpr int NN  = 100000;
constexpr int EE  = 1600000;
constexpr int EP  = EE + NN;
constexpr int HH  = 4;
constexpr int CC  = 32;
constexpr int HC  = 128;
constexpr int EDD = 16;
constexpr float SLOPE = 0.2f;
constexpr int SCAN_B = 1024;
constexpr int SCAN_G = (NN + SCAN_B - 1) / SCAN_B;   // 98

// ---------------- scratch ----------------
__device__ float g_h1[NN * HC];
__device__ float g_x1[NN * HC];
__device__ float g_g2[NN * CC];
__device__ float g_alS1[NN * HH], g_alD1[NN * HH];
__device__ float g_alS2[NN],      g_alD2[NN];
__device__ float g_alE1[EE * HH];
__device__ float g_alE2[EE];
__device__ float g_p1[EE * HH];      // exp(logit) per edge, layer 1
__device__ float g_p2[EE];           // exp(logit) per edge, layer 2
__device__ float g_v1e[EDD * HH];
__device__ float g_v2e[EDD];
__device__ int   g_deg[NN];
__device__ float g_aes1[NN * HH];
__device__ float g_aes2[NN];
__device__ float g_es1[NN * HH];
__device__ float g_z1[NN * HH];
__device__ float g_es2[NN];
__device__ float g_z2[NN];
// CSR over real edges only (no self loops)
__device__ int   g_count[NN];
__device__ int   g_rowptr[NN + 1];
__device__ int   g_cursor[NN];
__device__ int   g_cs[EE];           // src node per CSR slot
__device__ int   g_ce[EE];           // original edge id per CSR slot
__device__ int   g_bsum[128];

DINL float lrelu1(float x) { return x >= 0.f ? x : SLOPE * x; }
DINL float elu1(float x)   { return x > 0.f ? x : expm1f(x); }

// ---------------- zero scratch ----------------
__global__ void k_zero() {
    int t = blockIdx.x * blockDim.x + threadIdx.x;
    int stride = gridDim.x * blockDim.x;
    for (int i = t; i < NN * HH; i += stride) g_aes1[i] = 0.f;
    for (int i = t; i < NN;      i += stride) { g_aes2[i] = 0.f; g_deg[i] = 0; g_count[i] = 0; }
}

// ---------------- fold: v = We . a_e ----------------
__global__ void k_prep(const float* __restrict__ W1e, const float* __restrict__ a1e,
                       const float* __restrict__ W2e, const float* __restrict__ a2e) {
    int t = threadIdx.x;
    if (t < EDD * HH) {
        int d = t >> 2, h = t & 3;
        float s = 0.f;
        for (int c = 0; c < CC; c++) s += W1e[d * HC + h * CC + c] * a1e[h * CC + c];
        g_v1e[d * HH + h] = s;
    }
    if (t < EDD) {
        float s = 0.f;
        for (int c = 0; c < CC; c++) s += W2e[t * CC + c] * a2e[c];
        g_v2e[t] = s;
    }
}

// ---------------- per-edge logit contributions from edge_attr ----------------
__global__ void k_edge_al(const float* __restrict__ eattr) {
    int e = blockIdx.x * blockDim.x + threadIdx.x;
    if (e >= EE) return;
    const float* ea = eattr + e * EDD;
    float a0 = 0.f, a1 = 0.f, a2 = 0.f, a3 = 0.f, s2 = 0.f;
    #pragma unroll
    for (int d = 0; d < EDD; d++) {
        float ev = ea[d];
        a0 += ev * g_v1e[d * 4 + 0];
        a1 += ev * g_v1e[d * 4 + 1];
        a2 += ev * g_v1e[d * 4 + 2];
        a3 += ev * g_v1e[d * 4 + 3];
        s2 += ev * g_v2e[d];
    }
    g_alE1[e * 4 + 0] = a0;
    g_alE1[e * 4 + 1] = a1;
    g_alE1[e * 4 + 2] = a2;
    g_alE1[e * 4 + 3] = a3;
    g_alE2[e] = s2;
}

// ---------------- CSR build (real edges only) ----------------
__global__ void k_csr_count(const int* __restrict__ ei) {
    int e = blockIdx.x * blockDim.x + threadIdx.x;
    if (e < EE) atomicAdd(&g_count[ei[EE + e]], 1);
}
__global__ void k_scan_part() {
    __shared__ int sm[SCAN_B];
    int idx = blockIdx.x * SCAN_B + threadIdx.x;
    sm[threadIdx.x] = (idx < NN) ? g_count[idx] : 0;
    __syncthreads();
    for (int o = SCAN_B / 2; o; o >>= 1) {
        if (threadIdx.x < o) sm[threadIdx.x] += sm[threadIdx.x + o];
        __syncthreads();
    }
    if (threadIdx.x == 0) g_bsum[blockIdx.x] = sm[0];
}
__global__ void k_scan_top() {
    __shared__ int sm[128];
    int t = threadIdx.x;
    int v = (t < SCAN_G) ? g_bsum[t] : 0;
    sm[t] = v;
    __syncthreads();
    for (int o = 1; o < 128; o <<= 1) {
        int add = (t >= o) ? sm[t - o] : 0;
        __syncthreads();
        sm[t] += add;
        __syncthreads();
    }
    g_bsum[t] = sm[t] - v;   // exclusive block offsets
}
__global__ void k_scan_down() {
    __shared__ int sm[SCAN_B];
    int t = threadIdx.x;
    int idx = blockIdx.x * SCAN_B + t;
    int v = (idx < NN) ? g_count[idx] : 0;
    sm[t] = v;
    __syncthreads();
    for (int o = 1; o < SCAN_B; o <<= 1) {
        int add = (t >= o) ? sm[t - o] : 0;
        __syncthreads();
        sm[t] += add;
        __syncthreads();
    }
    if (idx < NN) g_rowptr[idx] = g_bsum[blockIdx.x] + sm[t] - v;  // exclusive
    if (idx == 0) g_rowptr[NN] = EE;
}
__global__ void k_cursor() {
    int n = blockIdx.x * blockDim.x + threadIdx.x;
    if (n < NN) g_cursor[n] = g_rowptr[n];
}
__global__ void k_csr_scatter(const int* __restrict__ ei) {
    int e = blockIdx.x * blockDim.x + threadIdx.x;
    if (e < EE) {
        int d = ei[EE + e];
        int pos = atomicAdd(&g_cursor[d], 1);
        g_cs[pos] = ei[e];
        g_ce[pos] = e;
    }
}

// ---------------- naive matmuls (proven correct in R9) ----------------
__global__ void k_mm1(const float* __restrict__ x, const float* __restrict__ W1) {
    int t = blockIdx.x * blockDim.x + threadIdx.x;
    if (t >= NN * HC) return;
    int n = t >> 7, j = t & 127;
    const float* xr = x + n * HC;
    float s = 0.f;
    #pragma unroll 8
    for (int k = 0; k < 128; k++) s += xr[k] * W1[k * HC + j];
    g_h1[t] = s;
}
__global__ void k_mm2(const float* __restrict__ W2) {
    int t = blockIdx.x * blockDim.x + threadIdx.x;
    if (t >= NN * CC) return;
    int n = t >> 5, j = t & 31;
    const float* xr = g_x1 + n * HC;
    float s = 0.f;
    #pragma unroll 8
    for (int k = 0; k < 128; k++) s += xr[k] * W2[k * CC + j];
    g_g2[t] = s;
}

// ---------------- per-node src/dst attention scalars ----------------
__global__ void k_nodal1(const float* __restrict__ a1s, const float* __restrict__ a1d) {
    int t = blockIdx.x * blockDim.x + threadIdx.x;
    if (t >= NN * HH) return;
    int n = t >> 2, h = t & 3;
    float s = 0.f, d = 0.f;
    for (int c = 0; c < CC; c++) {
        float hv = g_h1[n * HC + h * CC + c];
        s += hv * a1s[h * CC + c];
        d += hv * a1d[h * CC + c];
    }
    g_alS1[t] = s;
    g_alD1[t] = d;
}
__global__ void k_nodal2(const float* __restrict__ a2s, const float* __restrict__ a2d) {
    int n = blockIdx.x * blockDim.x + threadIdx.x;
    if (n >= NN) return;
    float s = 0.f, d = 0.f;
    for (int c = 0; c < CC; c++) {
        float gv = g_g2[n * CC + c];
        s += gv * a2s[c];
        d += gv * a2d[c];
    }
    g_alS2[n] = s;
    g_alD2[n] = d;
}

// ---------------- degree + sum of edge logit contributions per dst ----------------
__global__ void k_degsum(const int* __restrict__ ei) {
    int e = blockIdx.x * blockDim.x + threadIdx.x;
    if (e >= EE) return;
    int d = ei[EE + e];
    atomicAdd(&g_deg[d], 1);
    atomicAdd(&g_aes1[d * 4 + 0], g_alE1[e * 4 + 0]);
    atomicAdd(&g_aes1[d * 4 + 1], g_alE1[e * 4 + 1]);
    atomicAdd(&g_aes1[d * 4 + 2], g_alE1[e * 4 + 2]);
    atomicAdd(&g_aes1[d * 4 + 3], g_alE1[e * 4 + 3]);
    atomicAdd(&g_aes2[d], g_alE2[e]);
}

// ---------------- self-loop logits, init z with self term ----------------
__global__ void k_self1() {
    int t = blockIdx.x * blockDim.x + threadIdx.x;
    if (t >= NN * HH) return;
    int n = t >> 2;
    int dg = g_deg[n];
    float inv = 1.f / (float)(dg > 0 ? dg : 1);
    float es = lrelu1(g_alS1[t] + g_alD1[t] + g_aes1[t] * inv);
    g_es1[t] = es;
    g_z1[t]  = __expf(es);
}
__global__ void k_self2() {
    int n = blockIdx.x * blockDim.x + threadIdx.x;
    if (n >= NN) return;
    int dg = g_deg[n];
    float inv = 1.f / (float)(dg > 0 ? dg : 1);
    float es = lrelu1(g_alS2[n] + g_alD2[n] + g_aes2[n] * inv);
    g_es2[n] = es;
    g_z2[n]  = __expf(es);
}

// ---------------- softmax denominators + numerator cache ----------------
__global__ void k_z1(const int* __restrict__ ei) {
    int e = blockIdx.x * blockDim.x + threadIdx.x;
    if (e >= EE) return;
    int s = ei[e], d = ei[EE + e];
    #pragma unroll
    for (int h = 0; h < HH; h++) {
        float el = lrelu1(g_alS1[s * 4 + h] + g_alD1[d * 4 + h] + g_alE1[e * 4 + h]);
        float p = __expf(el);
        g_p1[e * 4 + h] = p;
        atomicAdd(&g_z1[d * 4 + h], p);
    }
}
__global__ void k_z2(const int* __restrict__ ei) {
    int e = blockIdx.x * blockDim.x + threadIdx.x;
    if (e >= EE) return;
    int s = ei[e], d = ei[EE + e];
    float el = lrelu1(g_alS2[s] + g_alD2[d] + g_alE2[e]);
    float p = __expf(el);
    g_p2[e] = p;
    atomicAdd(&g_z2[d], p);
}

// ---------------- CSR aggregation, fused epilogue (warp per node) ----------------
__global__ void k_agg1(const float* __restrict__ b1) {
    int n = (blockIdx.x * blockDim.x + threadIdx.x) >> 5;
    int lane = threadIdx.x & 31;
    if (n >= NN) return;
    int rs = g_rowptr[n], re = g_rowptr[n + 1];
    int h = lane >> 3;
    float iz = 1.f / g_z1[n * 4 + h];
    float pSelf = __expf(g_es1[n * 4 + h]);
    float4 hv = *(const float4*)&g_h1[n * HC + lane * 4];
    float4 acc = make_float4(pSelf * hv.x, pSelf * hv.y, pSelf * hv.z, pSelf * hv.w);
    for (int j = rs; j < re; j++) {
        int s = g_cs[j];
        int e = g_ce[j];
        float p = g_p1[e * 4 + h];
        float4 sv = *(const float4*)&g_h1[s * HC + lane * 4];
        acc.x += p * sv.x; acc.y += p * sv.y;
        acc.z += p * sv.z; acc.w += p * sv.w;
    }
    int j4 = lane * 4;
    g_x1[n * HC + j4 + 0] = elu1(acc.x * iz + b1[j4 + 0]);
    g_x1[n * HC + j4 + 1] = elu1(acc.y * iz + b1[j4 + 1]);
    g_x1[n * HC + j4 + 2] = elu1(acc.z * iz + b1[j4 + 2]);
    g_x1[n * HC + j4 + 3] = elu1(acc.w * iz + b1[j4 + 3]);
}
__global__ void k_agg2(const float* __restrict__ b2, float* __restrict__ h2out,
                       float* __restrict__ alphaOut) {
    int n = (blockIdx.x * blockDim.x + threadIdx.x) >> 5;
    int lane = threadIdx.x & 31;
    if (n >= NN) return;
    int rs = g_rowptr[n], re = g_rowptr[n + 1];
    float iz = 1.f / g_z2[n];
    float pSelf = __expf(g_es2[n]);
    float acc = pSelf * g_g2[n * CC + lane];
    bool wAl = (alphaOut != nullptr);
    for (int j = rs; j < re; j++) {
        int s = g_cs[j];
        int e = g_ce[j];
        float p = g_p2[e];
        acc += p * g_g2[s * CC + lane];
        if (wAl && lane == 0) alphaOut[e] = p * iz;
    }
    h2out[n * CC + lane] = elu1(acc * iz + b2[lane]);
    if (wAl && lane == 0) alphaOut[EE + n] = pSelf * iz;
}

// ---------------- edge_index output (as float) ----------------
__global__ void k_write_ei(const int* __restrict__ ei, float* __restrict__ out) {
    int t = blockIdx.x * blockDim.x + threadIdx.x;
    if (t >= EP) return;
    float sv = (t < EE) ? (float)ei[t]      : (float)(t - EE);
    float dv = (t < EE) ? (float)ei[EE + t] : (float)(t - EE);
    out[t] = sv;
    out[EP + t] = dv;
}

// ---------------- launch ----------------
extern "C" void kernel_launch(void* const* d_in, const int* in_sizes, int n_in,
                              void* d_out, int out_size) {
    const float* x    = (const float*)d_in[0];
    const int*   ei   = (const int*)d_in[1];
    const float* eattr= (const float*)d_in[2];
    const float* W1   = (const float*)d_in[3];
    const float* W1e  = (const float*)d_in[4];
    const float* a1s  = (const float*)d_in[5];
    const float* a1d  = (const float*)d_in[6];
    const float* a1e  = (const float*)d_in[7];
    const float* b1   = (const float*)d_in[8];
    const float* W2   = (const float*)d_in[9];
    const float* W2e  = (const float*)d_in[10];
    const float* a2s  = (const float*)d_in[11];
    const float* a2d  = (const float*)d_in[12];
    const float* a2e  = (const float*)d_in[13];
    const float* b2   = (const float*)d_in[14];
    float* out = (float*)d_out;

    bool hasEI = out_size >= NN * CC + 2 * EP;
    bool hasAl = out_size >= NN * CC + 2 * EP + EP;
    float* h2out  = out;
    float* eiout  = hasEI ? out + NN * CC : nullptr;
    float* alphaO = hasAl ? out + NN * CC + 2 * EP : nullptr;

    k_zero   <<<1024, 256>>>();
    k_prep   <<<1, 64>>>(W1e, a1e, W2e, a2e);
    k_edge_al<<<(EE + 255) / 256, 256>>>(eattr);

    // CSR build (real edges only)
    k_csr_count  <<<(EE + 255) / 256, 256>>>(ei);
    k_scan_part  <<<SCAN_G, SCAN_B>>>();
    k_scan_top   <<<1, 128>>>();
    k_scan_down  <<<SCAN_G, SCAN_B>>>();
    k_cursor     <<<(NN + 255) / 256, 256>>>();
    k_csr_scatter<<<(EE + 255) / 256, 256>>>(ei);

    // layer 1
    k_mm1    <<<(NN * HC + 255) / 256, 256>>>(x, W1);
    k_nodal1 <<<(NN * HH + 255) / 256, 256>>>(a1s, a1d);
    k_degsum <<<(EE + 255) / 256, 256>>>(ei);
    k_self1  <<<(NN * HH + 255) / 256, 256>>>();
    k_z1     <<<(EE + 255) / 256, 256>>>(ei);
    k_agg1   <<<(NN * 32 + 255) / 256, 256>>>(b1);

    // layer 2
    k_mm2    <<<(NN * CC + 255) / 256, 256>>>(W2);
    k_nodal2 <<<(NN + 255) / 256, 256>>>(a2s, a2d);
    k_self2  <<<(NN + 255) / 256, 256>>>();
    k_z2     <<<(EE + 255) / 256, 256>>>(ei);
    k_agg2   <<<(NN * 32 + 255) / 256, 256>>>(b2, h2out, alphaO);

    if (eiout) k_write_ei<<<(EP + 255) / 256, 256>>>(ei, eiout);
}

// round 13
// speedup vs baseline: 2.9408x; 1.9534x over previous
#include <cuda_runtime.h>
#include <math.h>

#define DINL __device__ __forceinline__

constexpr int NN  = 100000;
constexpr int EE  = 1600000;
constexpr int EP  = EE + NN;
constexpr int HH  = 4;
constexpr int CC  = 32;
constexpr int HC  = 128;
constexpr int EDD = 16;
constexpr float SLOPE = 0.2f;
constexpr int SCAN_B = 1024;
constexpr int SCAN_G = (NN + SCAN_B - 1) / SCAN_B;   // 98

// ---------------- scratch ----------------
__device__ float g_h1[NN * HC];
__device__ float g_x1[NN * HC];
__device__ float g_g2[NN * CC];
__device__ float g_alS1[NN * HH], g_alD1[NN * HH];
__device__ float g_alS2[NN],      g_alD2[NN];
__device__ float g_alE1[EE * HH];
__device__ float g_alE2[EE];
__device__ float g_p1c[EE * HH];     // exp(logit) per edge, CSR order, layer 1
__device__ float g_p2c[EE];          // exp(logit) per edge, CSR order, layer 2
__device__ float g_v1e[EDD * HH];
__device__ float g_v2e[EDD];
__device__ float g_aes1[NN * HH];
__device__ float g_aes2[NN];
__device__ float g_es1[NN * HH];
__device__ float g_es2[NN];
// CSR over real edges only (no self loops)
__device__ int   g_count[NN];        // in-degree (kept intact by scan)
__device__ int   g_rowptr[NN + 1];
__device__ int   g_cursor[NN];
__device__ int   g_cs[EE];           // src node per CSR slot
__device__ int   g_ce[EE];           // original edge id per CSR slot (alpha output only)
__device__ int   g_epos[EE];         // edge id -> CSR slot
__device__ int   g_bsum[128];

DINL float lrelu1(float x) { return x >= 0.f ? x : SLOPE * x; }
DINL float elu1(float x)   { return x > 0.f ? x : expm1f(x); }

// ---------------- zero scratch ----------------
__global__ void k_zero() {
    int t = blockIdx.x * blockDim.x + threadIdx.x;
    int stride = gridDim.x * blockDim.x;
    for (int i = t; i < NN * HH; i += stride) g_aes1[i] = 0.f;
    for (int i = t; i < NN;      i += stride) { g_aes2[i] = 0.f; g_count[i] = 0; }
}

// ---------------- fold: v = We . a_e ----------------
__global__ void k_prep(const float* __restrict__ W1e, const float* __restrict__ a1e,
                       const float* __restrict__ W2e, const float* __restrict__ a2e) {
    int t = threadIdx.x;
    if (t < EDD * HH) {
        int d = t >> 2, h = t & 3;
        float s = 0.f;
        for (int c = 0; c < CC; c++) s += W1e[d * HC + h * CC + c] * a1e[h * CC + c];
        g_v1e[d * HH + h] = s;
    }
    if (t < EDD) {
        float s = 0.f;
        for (int c = 0; c < CC; c++) s += W2e[t * CC + c] * a2e[c];
        g_v2e[t] = s;
    }
}

// ---------------- per-edge logit contributions + fused dst-sums ----------------
__global__ void k_edge_al(const float* __restrict__ eattr, const int* __restrict__ ei) {
    int e = blockIdx.x * blockDim.x + threadIdx.x;
    if (e >= EE) return;
    const float4* ea4 = (const float4*)(eattr + e * EDD);
    float a0 = 0.f, a1 = 0.f, a2 = 0.f, a3 = 0.f, s2 = 0.f;
    #pragma unroll
    for (int q = 0; q < 4; q++) {
        float4 v = ea4[q];
        int d0 = q * 4;
        a0 += v.x * g_v1e[d0 * 4 + 0] + v.y * g_v1e[(d0+1) * 4 + 0]
            + v.z * g_v1e[(d0+2) * 4 + 0] + v.w * g_v1e[(d0+3) * 4 + 0];
        a1 += v.x * g_v1e[d0 * 4 + 1] + v.y * g_v1e[(d0+1) * 4 + 1]
            + v.z * g_v1e[(d0+2) * 4 + 1] + v.w * g_v1e[(d0+3) * 4 + 1];
        a2 += v.x * g_v1e[d0 * 4 + 2] + v.y * g_v1e[(d0+1) * 4 + 2]
            + v.z * g_v1e[(d0+2) * 4 + 2] + v.w * g_v1e[(d0+3) * 4 + 2];
        a3 += v.x * g_v1e[d0 * 4 + 3] + v.y * g_v1e[(d0+1) * 4 + 3]
            + v.z * g_v1e[(d0+2) * 4 + 3] + v.w * g_v1e[(d0+3) * 4 + 3];
        s2 += v.x * g_v2e[d0] + v.y * g_v2e[d0+1] + v.z * g_v2e[d0+2] + v.w * g_v2e[d0+3];
    }
    *(float4*)&g_alE1[e * 4] = make_float4(a0, a1, a2, a3);
    g_alE2[e] = s2;
    int d = ei[EE + e];
    atomicAdd(&g_aes1[d * 4 + 0], a0);
    atomicAdd(&g_aes1[d * 4 + 1], a1);
    atomicAdd(&g_aes1[d * 4 + 2], a2);
    atomicAdd(&g_aes1[d * 4 + 3], a3);
    atomicAdd(&g_aes2[d], s2);
}

// ---------------- CSR build (real edges only) ----------------
__global__ void k_csr_count(const int* __restrict__ ei) {
    int e = blockIdx.x * blockDim.x + threadIdx.x;
    if (e < EE) atomicAdd(&g_count[ei[EE + e]], 1);
}
__global__ void k_scan_part() {
    __shared__ int sm[SCAN_B];
    int idx = blockIdx.x * SCAN_B + threadIdx.x;
    sm[threadIdx.x] = (idx < NN) ? g_count[idx] : 0;
    __syncthreads();
    for (int o = SCAN_B / 2; o; o >>= 1) {
        if (threadIdx.x < o) sm[threadIdx.x] += sm[threadIdx.x + o];
        __syncthreads();
    }
    if (threadIdx.x == 0) g_bsum[blockIdx.x] = sm[0];
}
__global__ void k_scan_top() {
    __shared__ int sm[128];
    int t = threadIdx.x;
    int v = (t < SCAN_G) ? g_bsum[t] : 0;
    sm[t] = v;
    __syncthreads();
    for (int o = 1; o < 128; o <<= 1) {
        int add = (t >= o) ? sm[t - o] : 0;
        __syncthreads();
        sm[t] += add;
        __syncthreads();
    }
    g_bsum[t] = sm[t] - v;   // exclusive block offsets
}
__global__ void k_scan_down() {
    __shared__ int sm[SCAN_B];
    int t = threadIdx.x;
    int idx = blockIdx.x * SCAN_B + t;
    int v = (idx < NN) ? g_count[idx] : 0;
    sm[t] = v;
    __syncthreads();
    for (int o = 1; o < SCAN_B; o <<= 1) {
        int add = (t >= o) ? sm[t - o] : 0;
        __syncthreads();
        sm[t] += add;
        __syncthreads();
    }
    if (idx < NN) g_rowptr[idx] = g_bsum[blockIdx.x] + sm[t] - v;  // exclusive
    if (idx == 0) g_rowptr[NN] = EE;
}
__global__ void k_cursor() {
    int n = blockIdx.x * blockDim.x + threadIdx.x;
    if (n < NN) g_cursor[n] = g_rowptr[n];
}
__global__ void k_csr_scatter(const int* __restrict__ ei) {
    int e = blockIdx.x * blockDim.x + threadIdx.x;
    if (e < EE) {
        int d = ei[EE + e];
        int pos = atomicAdd(&g_cursor[d], 1);
        g_cs[pos] = ei[e];
        g_ce[pos] = e;
        g_epos[e] = pos;
    }
}

// ---------------- register-blocked GEMMs (4 rows x 4 cols per thread) ----------------
// h1[n][j] = sum_k x[n][k] * W1[k][j],  NN % 4 == 0
__global__ void k_mm1(const float* __restrict__ x, const float* __restrict__ W1) {
    int t = blockIdx.x * blockDim.x + threadIdx.x;
    if (t >= (NN / 4) * 32) return;
    int nb = t >> 5;
    int j4 = (t & 31) * 4;
    int n0 = nb * 4;
    float4 acc[4];
    #pragma unroll
    for (int i = 0; i < 4; i++) acc[i] = make_float4(0.f, 0.f, 0.f, 0.f);
    for (int k = 0; k < 128; k += 4) {
        float4 xv[4];
        #pragma unroll
        for (int i = 0; i < 4; i++)
            xv[i] = *(const float4*)&x[(n0 + i) * 128 + k];
        #pragma unroll
        for (int kk = 0; kk < 4; kk++) {
            float4 w = *(const float4*)&W1[(k + kk) * 128 + j4];
            #pragma unroll
            for (int i = 0; i < 4; i++) {
                float xs = (kk == 0) ? xv[i].x : (kk == 1) ? xv[i].y : (kk == 2) ? xv[i].z : xv[i].w;
                acc[i].x += xs * w.x;
                acc[i].y += xs * w.y;
                acc[i].z += xs * w.z;
                acc[i].w += xs * w.w;
            }
        }
    }
    #pragma unroll
    for (int i = 0; i < 4; i++)
        *(float4*)&g_h1[(n0 + i) * 128 + j4] = acc[i];
}
// g2[n][j] = sum_k x1[n][k] * W2[k][j]
__global__ void k_mm2(const float* __restrict__ W2) {
    int t = blockIdx.x * blockDim.x + threadIdx.x;
    if (t >= (NN / 4) * 8) return;
    int nb = t >> 3;
    int j4 = (t & 7) * 4;
    int n0 = nb * 4;
    float4 acc[4];
    #pragma unroll
    for (int i = 0; i < 4; i++) acc[i] = make_float4(0.f, 0.f, 0.f, 0.f);
    for (int k = 0; k < 128; k += 4) {
        float4 xv[4];
        #pragma unroll
        for (int i = 0; i < 4; i++)
            xv[i] = *(const float4*)&g_x1[(n0 + i) * 128 + k];
        #pragma unroll
        for (int kk = 0; kk < 4; kk++) {
            float4 w = *(const float4*)&W2[(k + kk) * 32 + j4];
            #pragma unroll
            for (int i = 0; i < 4; i++) {
                float xs = (kk == 0) ? xv[i].x : (kk == 1) ? xv[i].y : (kk == 2) ? xv[i].z : xv[i].w;
                acc[i].x += xs * w.x;
                acc[i].y += xs * w.y;
                acc[i].z += xs * w.z;
                acc[i].w += xs * w.w;
            }
        }
    }
    #pragma unroll
    for (int i = 0; i < 4; i++)
        *(float4*)&g_g2[(n0 + i) * 32 + j4] = acc[i];
}

// ---------------- per-node src/dst attention scalars ----------------
__global__ void k_nodal1(const float* __restrict__ a1s, const float* __restrict__ a1d) {
    int t = blockIdx.x * blockDim.x + threadIdx.x;
    if (t >= NN * HH) return;
    int n = t >> 2, h = t & 3;
    float s = 0.f, d = 0.f;
    for (int c = 0; c < CC; c++) {
        float hv = g_h1[n * HC + h * CC + c];
        s += hv * a1s[h * CC + c];
        d += hv * a1d[h * CC + c];
    }
    g_alS1[t] = s;
    g_alD1[t] = d;
}
__global__ void k_nodal2(const float* __restrict__ a2s, const float* __restrict__ a2d) {
    int n = blockIdx.x * blockDim.x + threadIdx.x;
    if (n >= NN) return;
    float s = 0.f, d = 0.f;
    for (int c = 0; c < CC; c++) {
        float gv = g_g2[n * CC + c];
        s += gv * a2s[c];
        d += gv * a2d[c];
    }
    g_alS2[n] = s;
    g_alD2[n] = d;
}

// ---------------- self-loop logits ----------------
__global__ void k_self1() {
    int t = blockIdx.x * blockDim.x + threadIdx.x;
    if (t >= NN * HH) return;
    int n = t >> 2;
    int dg = g_count[n];
    float inv = 1.f / (float)(dg > 0 ? dg : 1);
    g_es1[t] = lrelu1(g_alS1[t] + g_alD1[t] + g_aes1[t] * inv);
}
__global__ void k_self2() {
    int n = blockIdx.x * blockDim.x + threadIdx.x;
    if (n >= NN) return;
    int dg = g_count[n];
    float inv = 1.f / (float)(dg > 0 ? dg : 1);
    g_es2[n] = lrelu1(g_alS2[n] + g_alD2[n] + g_aes2[n] * inv);
}

// ---------------- per-edge exp(logit), written in CSR order ----------------
__global__ void k_p1(const int* __restrict__ ei) {
    int e = blockIdx.x * blockDim.x + threadIdx.x;
    if (e >= EE) return;
    int s = ei[e], d = ei[EE + e];
    float4 as = *(const float4*)&g_alS1[s * 4];
    float4 ad = *(const float4*)&g_alD1[d * 4];
    float4 ae = *(const float4*)&g_alE1[e * 4];
    float4 p;
    p.x = __expf(lrelu1(as.x + ad.x + ae.x));
    p.y = __expf(lrelu1(as.y + ad.y + ae.y));
    p.z = __expf(lrelu1(as.z + ad.z + ae.z));
    p.w = __expf(lrelu1(as.w + ad.w + ae.w));
    *(float4*)&g_p1c[g_epos[e] * 4] = p;
}
__global__ void k_p2(const int* __restrict__ ei) {
    int e = blockIdx.x * blockDim.x + threadIdx.x;
    if (e >= EE) return;
    int s = ei[e], d = ei[EE + e];
    g_p2c[g_epos[e]] = __expf(lrelu1(g_alS2[s] + g_alD2[d] + g_alE2[e]));
}

// ---------------- CSR aggregation + in-warp softmax z + fused epilogue ----------------
__global__ void k_agg1(const float* __restrict__ b1) {
    int n = (blockIdx.x * blockDim.x + threadIdx.x) >> 5;
    int lane = threadIdx.x & 31;
    if (n >= NN) return;
    int rs = g_rowptr[n], re = g_rowptr[n + 1];
    int h = lane >> 3;
    float pSelf = __expf(g_es1[n * 4 + h]);
    float4 hv = *(const float4*)&g_h1[n * HC + lane * 4];
    float4 acc = make_float4(pSelf * hv.x, pSelf * hv.y, pSelf * hv.z, pSelf * hv.w);
    float zsum = pSelf;
    for (int j = rs; j < re; j++) {
        int s = g_cs[j];
        float p = g_p1c[j * 4 + h];
        float4 sv = *(const float4*)&g_h1[s * HC + lane * 4];
        acc.x += p * sv.x; acc.y += p * sv.y;
        acc.z += p * sv.z; acc.w += p * sv.w;
        zsum += p;
    }
    float iz = 1.f / zsum;
    int j4 = lane * 4;
    g_x1[n * HC + j4 + 0] = elu1(acc.x * iz + b1[j4 + 0]);
    g_x1[n * HC + j4 + 1] = elu1(acc.y * iz + b1[j4 + 1]);
    g_x1[n * HC + j4 + 2] = elu1(acc.z * iz + b1[j4 + 2]);
    g_x1[n * HC + j4 + 3] = elu1(acc.w * iz + b1[j4 + 3]);
}
__global__ void k_agg2(const float* __restrict__ b2, float* __restrict__ h2out,
                       float* __restrict__ alphaOut) {
    int n = (blockIdx.x * blockDim.x + threadIdx.x) >> 5;
    int lane = threadIdx.x & 31;
    if (n >= NN) return;
    int rs = g_rowptr[n], re = g_rowptr[n + 1];
    float pSelf = __expf(g_es2[n]);
    float acc = pSelf * g_g2[n * CC + lane];
    float zsum = pSelf;
    for (int j = rs; j < re; j++) {
        int s = g_cs[j];
        float p = g_p2c[j];
        acc += p * g_g2[s * CC + lane];
        zsum += p;
    }
    float iz = 1.f / zsum;
    h2out[n * CC + lane] = elu1(acc * iz + b2[lane]);
    if (alphaOut != nullptr) {
        for (int j = rs + lane; j < re; j += 32)
            alphaOut[g_ce[j]] = g_p2c[j] * iz;
        if (lane == 0) alphaOut[EE + n] = pSelf * iz;
    }
}

// ---------------- edge_index output (as float) ----------------
__global__ void k_write_ei(const int* __restrict__ ei, float* __restrict__ out) {
    int t = blockIdx.x * blockDim.x + threadIdx.x;
    if (t >= EP) return;
    float sv = (t < EE) ? (float)ei[t]      : (float)(t - EE);
    float dv = (t < EE) ? (float)ei[EE + t] : (float)(t - EE);
    out[t] = sv;
    out[EP + t] = dv;
}

// ---------------- launch ----------------
extern "C" void kernel_launch(void* const* d_in, const int* in_sizes, int n_in,
                              void* d_out, int out_size) {
    const float* x    = (const float*)d_in[0];
    const int*   ei   = (const int*)d_in[1];
    const float* eattr= (const float*)d_in[2];
    const float* W1   = (const float*)d_in[3];
    const float* W1e  = (const float*)d_in[4];
    const float* a1s  = (const float*)d_in[5];
    const float* a1d  = (const float*)d_in[6];
    const float* a1e  = (const float*)d_in[7];
    const float* b1   = (const float*)d_in[8];
    const float* W2   = (const float*)d_in[9];
    const float* W2e  = (const float*)d_in[10];
    const float* a2s  = (const float*)d_in[11];
    const float* a2d  = (const float*)d_in[12];
    const float* a2e  = (const float*)d_in[13];
    const float* b2   = (const float*)d_in[14];
    float* out = (float*)d_out;

    bool hasEI = out_size >= NN * CC + 2 * EP;
    bool hasAl = out_size >= NN * CC + 2 * EP + EP;
    float* h2out  = out;
    float* eiout  = hasEI ? out + NN * CC : nullptr;
    float* alphaO = hasAl ? out + NN * CC + 2 * EP : nullptr;

    k_zero   <<<1024, 256>>>();
    k_prep   <<<1, 64>>>(W1e, a1e, W2e, a2e);

    // CSR build (real edges only); g_count survives as in-degree
    k_csr_count  <<<(EE + 255) / 256, 256>>>(ei);
    k_scan_part  <<<SCAN_G, SCAN_B>>>();
    k_scan_top   <<<1, 128>>>();
    k_scan_down  <<<SCAN_G, SCAN_B>>>();
    k_cursor     <<<(NN + 255) / 256, 256>>>();
    k_csr_scatter<<<(EE + 255) / 256, 256>>>(ei);

    k_edge_al<<<(EE + 255) / 256, 256>>>(eattr, ei);

    // layer 1
    k_mm1    <<<((NN / 4) * 32 + 255) / 256, 256>>>(x, W1);
    k_nodal1 <<<(NN * HH + 255) / 256, 256>>>(a1s, a1d);
    k_self1  <<<(NN * HH + 255) / 256, 256>>>();
    k_p1     <<<(EE + 255) / 256, 256>>>(ei);
    k_agg1   <<<(NN * 32 + 255) / 256, 256>>>(b1);

    // layer 2
    k_mm2    <<<((NN / 4) * 8 + 255) / 256, 256>>>(W2);
    k_nodal2 <<<(NN + 255) / 256, 256>>>(a2s, a2d);
    k_self2  <<<(NN + 255) / 256, 256>>>();
    k_p2     <<<(EE + 255) / 256, 256>>>(ei);
    k_agg2   <<<(NN * 32 + 255) / 256, 256>>>(b2, h2out, alphaO);

    if (eiout) k_write_ei<<<(EP + 255) / 256, 256>>>(ei, eiout);
}